// round 4
// baseline (speedup 1.0000x reference)
#include <cuda_runtime.h>

#define LQ  2048
#define SK  2048
#define NB  4
#define EMB 512
#define NH  16
#define HD  32
#define ROWS (LQ * NB)   // 8192

// Scratch (allocation-free rule: __device__ globals)
__device__ float g_Q[NB * NH * LQ * HD];   // [n,h,l,d]
__device__ float g_K[NB * NH * SK * HD];   // [n,h,s,d]
__device__ float g_V[NB * NH * SK * HD];
__device__ float g_O[ROWS * EMB];          // attention output, (l*NB+n, e) row-major

// ---------------------------------------------------------------------------
// tf32 helpers
// ---------------------------------------------------------------------------
__device__ __forceinline__ unsigned f2tf(float x) {
    unsigned r;
    asm("cvt.rna.tf32.f32 %0, %1;" : "=r"(r) : "f"(x));
    return r;
}
__device__ __forceinline__ void mma_tf32(float* c, const unsigned* a,
                                         unsigned b0, unsigned b1) {
    asm volatile(
        "mma.sync.aligned.m16n8k8.row.col.f32.tf32.tf32.f32 "
        "{%0,%1,%2,%3}, {%4,%5,%6,%7}, {%8,%9}, {%0,%1,%2,%3};"
        : "+f"(c[0]), "+f"(c[1]), "+f"(c[2]), "+f"(c[3])
        : "r"(a[0]), "r"(a[1]), "r"(a[2]), "r"(a[3]), "r"(b0), "r"(b1));
}

// ---------------------------------------------------------------------------
// 3xTF32 tensor-core GEMM: out[r,f] = sum_e A[r,e] * W[f,e] + bias[f]
// BM=128, BN=64, BK=16, 256 threads (8 warps: 4 along M x 2 along N).
// Each warp: 32x32 = 2 m-tiles x 4 n-tiles of m16n8k8, 3 compensation passes.
// MODE 0: QKV projection (z picks input/weight-slice/dest, scatter epilogue)
// MODE 1: out-projection (A = g_O, row-major output)
// ---------------------------------------------------------------------------
template<int MODE>
__global__ __launch_bounds__(256)
void gemm_mma_kernel(const float* __restrict__ Aq, const float* __restrict__ Ak,
                     const float* __restrict__ Av, const float* __restrict__ Wfull,
                     const float* __restrict__ bfull, float* __restrict__ outp)
{
    __shared__ float Ah[16][136];  // [k][m], pad 136 -> conflict-free frag LDS
    __shared__ float Al[16][136];
    __shared__ float Bh[16][72];   // [k][n], pad 72
    __shared__ float Bl[16][72];

    const int tid  = threadIdx.x;
    const int warp = tid >> 5;
    const int lane = tid & 31;
    const int g    = lane >> 2;   // 0..7
    const int t    = lane & 3;    // 0..3
    const int wm   = (warp >> 1) * 32;  // warp m-offset in tile
    const int wn   = (warp & 1) * 32;   // warp n-offset in tile
    const int r0   = blockIdx.x * 128;
    const int f0   = blockIdx.y * 64;

    const float* A;
    const float* W;
    const float* bias;
    if (MODE == 0) {
        const int z = blockIdx.z;
        A    = (z == 0) ? Aq : (z == 1) ? Ak : Av;
        W    = Wfull + z * EMB * EMB;
        bias = bfull + z * EMB;
    } else {
        A    = g_O;
        W    = Wfull;
        bias = bfull;
    }

    float acc[2][4][4];
    #pragma unroll
    for (int mi = 0; mi < 2; mi++)
        #pragma unroll
        for (int ni = 0; ni < 4; ni++)
            #pragma unroll
            for (int j = 0; j < 4; j++) acc[mi][ni][j] = 0.f;

    for (int k0 = 0; k0 < EMB; k0 += 16) {
        // A tile: 128x16, 512 float4 loads (2/thread), split hi/lo, store [k][m]
        #pragma unroll
        for (int tt = tid; tt < 512; tt += 256) {
            const int row = tt >> 2;
            const int kk  = (tt & 3) << 2;
            const float4 v = *(const float4*)(A + (size_t)(r0 + row) * EMB + k0 + kk);
            const float x[4] = {v.x, v.y, v.z, v.w};
            #pragma unroll
            for (int j = 0; j < 4; j++) {
                const float h = __uint_as_float(f2tf(x[j]));
                Ah[kk + j][row] = h;
                Al[kk + j][row] = __uint_as_float(f2tf(x[j] - h));
            }
        }
        // B tile: 64x16, 256 float4 loads (1/thread)
        {
            const int n  = tid >> 2;
            const int kk = (tid & 3) << 2;
            const float4 v = *(const float4*)(W + (size_t)(f0 + n) * EMB + k0 + kk);
            const float x[4] = {v.x, v.y, v.z, v.w};
            #pragma unroll
            for (int j = 0; j < 4; j++) {
                const float h = __uint_as_float(f2tf(x[j]));
                Bh[kk + j][n] = h;
                Bl[kk + j][n] = __uint_as_float(f2tf(x[j] - h));
            }
        }
        __syncthreads();

        #pragma unroll
        for (int ks = 0; ks < 2; ks++) {
            const int kb = ks * 8;
            unsigned ah[2][4], al[2][4];
            #pragma unroll
            for (int mi = 0; mi < 2; mi++) {
                const int m = wm + mi * 16 + g;
                ah[mi][0] = __float_as_uint(Ah[kb + t][m]);
                ah[mi][1] = __float_as_uint(Ah[kb + t][m + 8]);
                ah[mi][2] = __float_as_uint(Ah[kb + t + 4][m]);
                ah[mi][3] = __float_as_uint(Ah[kb + t + 4][m + 8]);
                al[mi][0] = __float_as_uint(Al[kb + t][m]);
                al[mi][1] = __float_as_uint(Al[kb + t][m + 8]);
                al[mi][2] = __float_as_uint(Al[kb + t + 4][m]);
                al[mi][3] = __float_as_uint(Al[kb + t + 4][m + 8]);
            }
            #pragma unroll
            for (int ni = 0; ni < 4; ni++) {
                const int n = wn + ni * 8 + g;
                const unsigned bh0 = __float_as_uint(Bh[kb + t][n]);
                const unsigned bh1 = __float_as_uint(Bh[kb + t + 4][n]);
                const unsigned bl0 = __float_as_uint(Bl[kb + t][n]);
                const unsigned bl1 = __float_as_uint(Bl[kb + t + 4][n]);
                #pragma unroll
                for (int mi = 0; mi < 2; mi++) {
                    mma_tf32(acc[mi][ni], ah[mi], bh0, bh1);
                    mma_tf32(acc[mi][ni], ah[mi], bl0, bl1);
                    mma_tf32(acc[mi][ni], al[mi], bh0, bh1);
                }
            }
        }
        __syncthreads();
    }

    // Epilogue: c0=(g,2t) c1=(g,2t+1) c2=(g+8,2t) c3=(g+8,2t+1)
    #pragma unroll
    for (int mi = 0; mi < 2; mi++) {
        #pragma unroll
        for (int ni = 0; ni < 4; ni++) {
            const float* c = acc[mi][ni];
            const int f  = f0 + wn + ni * 8 + 2 * t;
            const float b0 = bias[f];
            const float b1 = bias[f + 1];
            const int rA = r0 + wm + mi * 16 + g;
            const int rB = rA + 8;
            if (MODE == 0) {
                float* dst = (blockIdx.z == 0) ? g_Q : (blockIdx.z == 1) ? g_K : g_V;
                const int h = f >> 5;
                const int d = f & 31;   // even, d+1 same head
                {
                    const int l = rA >> 2, n = rA & 3;
                    *(float2*)(dst + ((size_t)(n * NH + h) * LQ + l) * HD + d) =
                        make_float2(c[0] + b0, c[1] + b1);
                }
                {
                    const int l = rB >> 2, n = rB & 3;
                    *(float2*)(dst + ((size_t)(n * NH + h) * LQ + l) * HD + d) =
                        make_float2(c[2] + b0, c[3] + b1);
                }
            } else {
                *(float2*)(outp + (size_t)rA * EMB + f) = make_float2(c[0] + b0, c[1] + b1);
                *(float2*)(outp + (size_t)rB * EMB + f) = make_float2(c[2] + b0, c[3] + b1);
            }
        }
    }
}

// ---------------------------------------------------------------------------
// LayerNorm over D=32 for K and V (one warp per row)
// ---------------------------------------------------------------------------
__global__ __launch_bounds__(256)
void ln_kernel(const float* __restrict__ w, const float* __restrict__ b)
{
    const int gw   = (blockIdx.x * blockDim.x + threadIdx.x) >> 5;
    const int lane = threadIdx.x & 31;
    const int R    = NB * NH * SK;
    if (gw >= 2 * R) return;
    float* X      = (gw < R) ? g_K : g_V;
    const int row = (gw < R) ? gw : gw - R;

    float x = X[(size_t)row * HD + lane];
    float s = x;
    #pragma unroll
    for (int o = 16; o; o >>= 1) s += __shfl_xor_sync(0xffffffffu, s, o);
    const float mu = s * (1.0f / HD);
    const float dv = x - mu;
    float vv = dv * dv;
    #pragma unroll
    for (int o = 16; o; o >>= 1) vv += __shfl_xor_sync(0xffffffffu, vv, o);
    const float inv = rsqrtf(vv * (1.0f / HD) + 1e-5f);
    X[(size_t)row * HD + lane] = dv * inv * w[lane] + b[lane];
}

// ---------------------------------------------------------------------------
// Flash attention, tf32 mma.sync. QK^T uses 3xTF32 compensation (hi/lo split
// of both Q and K) so score error is fp32-level; PV stays single tf32
// (statistical cancellation keeps its contribution ~1e-4).
// Block = 128 thr (4 warps), each warp 16 q rows. S chunks of 64 in smem.
// ---------------------------------------------------------------------------
__global__ __launch_bounds__(128)
void attn_mma_kernel(const float* __restrict__ scaling)
{
    __shared__ float Kh[64][36];
    __shared__ float Kl[64][36];
    __shared__ float Vs[64][36];

    const int tid  = threadIdx.x;
    const int warp = tid >> 5;
    const int lane = tid & 31;
    const int g    = lane >> 2;
    const int t    = lane & 3;
    const int nh   = blockIdx.y;   // n*NH + h
    const int h    = nh & (NH - 1);
    const float beta = scaling[h];
    const int q0   = blockIdx.x * 64 + warp * 16;

    // Q A-fragments (4 k-steps over D=32), beta-scaled, hi/lo tf32 split
    const float* Qp = g_Q + ((size_t)nh * LQ + q0) * HD;
    unsigned aqh[4][4], aql[4][4];
    #pragma unroll
    for (int ks = 0; ks < 4; ks++) {
        const float q00 = Qp[(size_t)g       * HD + ks * 8 + t]     * beta;
        const float q10 = Qp[(size_t)(g + 8) * HD + ks * 8 + t]     * beta;
        const float q01 = Qp[(size_t)g       * HD + ks * 8 + t + 4] * beta;
        const float q11 = Qp[(size_t)(g + 8) * HD + ks * 8 + t + 4] * beta;
        aqh[ks][0] = f2tf(q00);
        aqh[ks][1] = f2tf(q10);
        aqh[ks][2] = f2tf(q01);
        aqh[ks][3] = f2tf(q11);
        aql[ks][0] = f2tf(q00 - __uint_as_float(aqh[ks][0]));
        aql[ks][1] = f2tf(q10 - __uint_as_float(aqh[ks][1]));
        aql[ks][2] = f2tf(q01 - __uint_as_float(aqh[ks][2]));
        aql[ks][3] = f2tf(q11 - __uint_as_float(aqh[ks][3]));
    }

    float m0 = -1e30f, m1 = -1e30f, l0 = 0.f, l1 = 0.f;
    float o[4][4];
    #pragma unroll
    for (int nd = 0; nd < 4; nd++)
        #pragma unroll
        for (int j = 0; j < 4; j++) o[nd][j] = 0.f;

    const float* Kb = g_K + (size_t)nh * SK * HD;
    const float* Vb = g_V + (size_t)nh * SK * HD;

    for (int s0 = 0; s0 < SK; s0 += 64) {
        // Cooperative load: K split hi/lo, V tf32-rounded
        #pragma unroll
        for (int i = tid; i < 512; i += 128) {
            const int row = i >> 3;
            const int dc  = (i & 7) << 2;
            const float4 kv = *(const float4*)(Kb + (size_t)(s0 + row) * HD + dc);
            float4 khi, klo;
            khi.x = __uint_as_float(f2tf(kv.x)); klo.x = __uint_as_float(f2tf(kv.x - khi.x));
            khi.y = __uint_as_float(f2tf(kv.y)); klo.y = __uint_as_float(f2tf(kv.y - khi.y));
            khi.z = __uint_as_float(f2tf(kv.z)); klo.z = __uint_as_float(f2tf(kv.z - khi.z));
            khi.w = __uint_as_float(f2tf(kv.w)); klo.w = __uint_as_float(f2tf(kv.w - khi.w));
            *(float4*)&Kh[row][dc] = khi;
            *(float4*)&Kl[row][dc] = klo;
            float4 vv = *(const float4*)(Vb + (size_t)(s0 + row) * HD + dc);
            vv.x = __uint_as_float(f2tf(vv.x));
            vv.y = __uint_as_float(f2tf(vv.y));
            vv.z = __uint_as_float(f2tf(vv.z));
            vv.w = __uint_as_float(f2tf(vv.w));
            *(float4*)&Vs[row][dc] = vv;
        }
        __syncthreads();

        // Scores: 8 n-tiles of 16x8; per (nd,ks): 3 compensation MMAs
        float sc[8][4];
        #pragma unroll
        for (int nd = 0; nd < 8; nd++) {
            sc[nd][0] = sc[nd][1] = sc[nd][2] = sc[nd][3] = 0.f;
            #pragma unroll
            for (int ks = 0; ks < 4; ks++) {
                const unsigned bh0 = __float_as_uint(Kh[nd * 8 + g][ks * 8 + t]);
                const unsigned bh1 = __float_as_uint(Kh[nd * 8 + g][ks * 8 + t + 4]);
                const unsigned bl0 = __float_as_uint(Kl[nd * 8 + g][ks * 8 + t]);
                const unsigned bl1 = __float_as_uint(Kl[nd * 8 + g][ks * 8 + t + 4]);
                mma_tf32(sc[nd], aqh[ks], bh0, bh1);
                mma_tf32(sc[nd], aqh[ks], bl0, bl1);
                mma_tf32(sc[nd], aql[ks], bh0, bh1);
            }
        }

        // Online softmax (rows g: sc[.][0,1]; rows g+8: sc[.][2,3])
        float t0 = -1e30f, t1 = -1e30f;
        #pragma unroll
        for (int nd = 0; nd < 8; nd++) {
            t0 = fmaxf(t0, fmaxf(sc[nd][0], sc[nd][1]));
            t1 = fmaxf(t1, fmaxf(sc[nd][2], sc[nd][3]));
        }
        t0 = fmaxf(t0, __shfl_xor_sync(0xffffffffu, t0, 1));
        t0 = fmaxf(t0, __shfl_xor_sync(0xffffffffu, t0, 2));
        t1 = fmaxf(t1, __shfl_xor_sync(0xffffffffu, t1, 1));
        t1 = fmaxf(t1, __shfl_xor_sync(0xffffffffu, t1, 2));

        const float nm0 = fmaxf(m0, t0);
        const float nm1 = fmaxf(m1, t1);
        const float c0  = __expf(m0 - nm0);
        const float c1  = __expf(m1 - nm1);

        float rs0 = 0.f, rs1 = 0.f;
        #pragma unroll
        for (int nd = 0; nd < 8; nd++) {
            sc[nd][0] = __expf(sc[nd][0] - nm0);
            sc[nd][1] = __expf(sc[nd][1] - nm0);
            sc[nd][2] = __expf(sc[nd][2] - nm1);
            sc[nd][3] = __expf(sc[nd][3] - nm1);
            rs0 += sc[nd][0] + sc[nd][1];
            rs1 += sc[nd][2] + sc[nd][3];
        }
        rs0 += __shfl_xor_sync(0xffffffffu, rs0, 1);
        rs0 += __shfl_xor_sync(0xffffffffu, rs0, 2);
        rs1 += __shfl_xor_sync(0xffffffffu, rs1, 1);
        rs1 += __shfl_xor_sync(0xffffffffu, rs1, 2);

        l0 = l0 * c0 + rs0;
        l1 = l1 * c1 + rs1;
        #pragma unroll
        for (int nd = 0; nd < 4; nd++) {
            o[nd][0] *= c0; o[nd][1] *= c0;
            o[nd][2] *= c1; o[nd][3] *= c1;
        }
        m0 = nm0; m1 = nm1;

        // PV: C-frag -> A-frag via intra-quad shuffles, single tf32
        const int sA = t >> 1;
        const int sB = sA + 2;
        const bool odd = (t & 1);
        #pragma unroll
        for (int kst = 0; kst < 8; kst++) {
            const float p0 = sc[kst][0], p1 = sc[kst][1];
            const float p2 = sc[kst][2], p3 = sc[kst][3];
            const float x0 = __shfl_sync(0xffffffffu, p0, sA, 4);
            const float x1 = __shfl_sync(0xffffffffu, p1, sA, 4);
            const float y0 = __shfl_sync(0xffffffffu, p0, sB, 4);
            const float y1 = __shfl_sync(0xffffffffu, p1, sB, 4);
            const float z0 = __shfl_sync(0xffffffffu, p2, sA, 4);
            const float z1 = __shfl_sync(0xffffffffu, p3, sA, 4);
            const float w0 = __shfl_sync(0xffffffffu, p2, sB, 4);
            const float w1 = __shfl_sync(0xffffffffu, p3, sB, 4);
            unsigned ap[4];
            ap[0] = f2tf(odd ? x1 : x0);
            ap[1] = f2tf(odd ? z1 : z0);
            ap[2] = f2tf(odd ? y1 : y0);
            ap[3] = f2tf(odd ? w1 : w0);
            #pragma unroll
            for (int nd = 0; nd < 4; nd++) {
                const unsigned b0 = __float_as_uint(Vs[kst * 8 + t][nd * 8 + g]);
                const unsigned b1 = __float_as_uint(Vs[kst * 8 + t + 4][nd * 8 + g]);
                mma_tf32(o[nd], ap, b0, b1);
            }
        }
        __syncthreads();
    }

    // Epilogue
    const float i0 = 1.0f / l0;
    const float i1 = 1.0f / l1;
    const int n = nh >> 4;
    float* op0 = g_O + ((size_t)(q0 + g)     * NB + n) * EMB + h * HD;
    float* op1 = g_O + ((size_t)(q0 + g + 8) * NB + n) * EMB + h * HD;
    #pragma unroll
    for (int nd = 0; nd < 4; nd++) {
        const int col = nd * 8 + 2 * t;
        *(float2*)(op0 + col) = make_float2(o[nd][0] * i0, o[nd][1] * i0);
        *(float2*)(op1 + col) = make_float2(o[nd][2] * i1, o[nd][3] * i1);
    }
}

// ---------------------------------------------------------------------------
extern "C" void kernel_launch(void* const* d_in, const int* in_sizes, int n_in,
                              void* d_out, int out_size)
{
    const float* query   = (const float*)d_in[0];
    const float* key_in  = (const float*)d_in[1];
    const float* value   = (const float*)d_in[2];
    const float* scaling = (const float*)d_in[3];
    const float* in_w    = (const float*)d_in[4];
    const float* in_b    = (const float*)d_in[5];
    const float* pn_w    = (const float*)d_in[6];
    const float* pn_b    = (const float*)d_in[7];
    const float* out_w   = (const float*)d_in[8];
    const float* out_b   = (const float*)d_in[9];
    float* out = (float*)d_out;

    // 1) QKV projections -> scratch in [n,h,len,d]
    dim3 gproj(ROWS / 128, EMB / 64, 3);
    gemm_mma_kernel<0><<<gproj, 256>>>(query, key_in, value, in_w, in_b, nullptr);

    // 2) LayerNorm K and V over D
    const int ln_rows = 2 * NB * NH * SK;
    ln_kernel<<<ln_rows / 8, 256>>>(pn_w, pn_b);

    // 3) Flash attention (tf32 tensor-core, 3xTF32 scores)
    dim3 gattn(LQ / 64, NB * NH);
    attn_mma_kernel<<<gattn, 128>>>(scaling);

    // 4) Output projection -> d_out
    dim3 gout(ROWS / 128, EMB / 64, 1);
    gemm_mma_kernel<1><<<gout, 256>>>(nullptr, nullptr, nullptr, out_w, out_b, out);
}